// round 12
// baseline (speedup 1.0000x reference)
#include <cuda_runtime.h>
#include <math.h>

#define B 4
#define S 2048
#define D 512
#define H 8
#define A 64
#define HA (H*A)

// Scratch (allocation-free rule: __device__ globals)
__device__ float g_q[(size_t)B*H*S*A];     // proj outputs, tf32-rounded
__device__ float g_k[(size_t)B*H*S*A];
__device__ float g_v[(size_t)B*H*A*S];     // V TRANSPOSED: [bh][d][s]
__device__ float g_attn[(size_t)B*S*HA];   // attention out, tf32-rounded
// tf32-rounded inputs
__device__ float g_xq[(size_t)B*S*D];
__device__ float g_xk[(size_t)B*S*D];
__device__ float g_xv[(size_t)B*S*D];
// tf32-rounded TRANSPOSED weights (n-major for ldmatrix B-operands)
__device__ float g_wq[(size_t)H*A*D];      // [h][a][d]
__device__ float g_wk[(size_t)H*A*D];
__device__ float g_wv[(size_t)H*A*D];
__device__ float g_wo[(size_t)D*HA];       // [d_out][ha]

// ---------------------------------------------------------------------------
// helpers
// ---------------------------------------------------------------------------
__device__ __forceinline__ unsigned f2tf(float x) {
    unsigned u;
    asm("cvt.rna.tf32.f32 %0, %1;" : "=r"(u) : "f"(x));
    return u;
}

__device__ __forceinline__ void mma_tf32(float c[4], const unsigned a[4],
                                         unsigned b0, unsigned b1) {
    asm volatile("mma.sync.aligned.m16n8k8.row.col.f32.tf32.tf32.f32 "
                 "{%0,%1,%2,%3}, {%4,%5,%6,%7}, {%8,%9}, {%0,%1,%2,%3};"
                 : "+f"(c[0]), "+f"(c[1]), "+f"(c[2]), "+f"(c[3])
                 : "r"(a[0]), "r"(a[1]), "r"(a[2]), "r"(a[3]),
                   "r"(b0), "r"(b1));
}

// ldmatrix x4 on fp32 data viewed as b16.
__device__ __forceinline__ void ldsm4(unsigned r[4], unsigned saddr) {
    asm volatile("ldmatrix.sync.aligned.m8n8.x4.shared.b16 {%0,%1,%2,%3}, [%4];"
                 : "=r"(r[0]), "=r"(r[1]), "=r"(r[2]), "=r"(r[3])
                 : "r"(saddr));
}

__device__ __forceinline__ void cpa16(float* dst_smem, const float* src) {
    unsigned d = (unsigned)__cvta_generic_to_shared(dst_smem);
    asm volatile("cp.async.cg.shared.global [%0], [%1], 16;" :: "r"(d), "l"(src));
}
#define CPA_COMMIT() asm volatile("cp.async.commit_group;")
#define CPA_WAIT(n)  asm volatile("cp.async.wait_group %0;" :: "n"(n))

// SWL: XOR bits [2:4] of word-col by row&7 -> ldmatrix tiles conflict-free.
#define SWL(r, c) ((r)*64 + ((c) ^ (((r)&7) << 2)))
#define FU(x) __float_as_uint(x)

// ---------------------------------------------------------------------------
// Kernel 0: fused prep — round x tensors + transpose-round all weights.
// ---------------------------------------------------------------------------
#define NX4 ((B*S*D)/4)
#define NXB (3*NX4/256)          // 12288 rounding blocks
__global__ void __launch_bounds__(256) prep_kernel(
    const float* __restrict__ q, const float* __restrict__ k,
    const float* __restrict__ v,
    const float* __restrict__ wq, const float* __restrict__ wk,
    const float* __restrict__ wv, const float* __restrict__ wo)
{
    const int bid = blockIdx.x;
    const int tid = threadIdx.x;
    if (bid < NXB) {
        int i = bid * 256 + tid;
        const float* src; float* dst; int off;
        if      (i < 1*NX4) { src = q; dst = g_xq; off = i;         }
        else if (i < 2*NX4) { src = k; dst = g_xk; off = i - NX4;   }
        else                { src = v; dst = g_xv; off = i - 2*NX4; }
        float4 val = ((const float4*)src)[off];
        val.x = __uint_as_float(f2tf(val.x));
        val.y = __uint_as_float(f2tf(val.y));
        val.z = __uint_as_float(f2tf(val.z));
        val.w = __uint_as_float(f2tf(val.w));
        ((float4*)dst)[off] = val;
        return;
    }
    // weight transpose: src MxN (k-major) -> dst NxM (n-major), rounded
    __shared__ float ts[32][33];
    const int t = bid - NXB;
    const float* src; float* dst; int M, N, tr, tc;
    if (t < 768) {
        int p = t / 256, rem = t % 256;
        int h = rem / 32, tile = rem % 32;
        tr = tile % 16; tc = tile / 16;          // 16 x 2 tiles (512x64)
        M = D; N = A;
        src = (p == 0 ? wq : p == 1 ? wk : wv) + (size_t)h * D * A;
        dst = (p == 0 ? g_wq : p == 1 ? g_wk : g_wv) + (size_t)h * A * D;
    } else {
        int u = t - 768;
        tr = u % 16; tc = u / 16;                // 16 x 16 tiles (512x512)
        M = HA; N = D;
        src = wo; dst = g_wo;
    }
    const int tx = tid & 31, ty = tid >> 5;
    #pragma unroll
    for (int i = ty; i < 32; i += 8)
        ts[i][tx] = src[(size_t)(tr*32 + i) * N + tc*32 + tx];
    __syncthreads();
    #pragma unroll
    for (int i = ty; i < 32; i += 8)
        dst[(size_t)(tc*32 + i) * M + tr*32 + tx] =
            __uint_as_float(f2tf(ts[tx][i]));
}

// ---------------------------------------------------------------------------
// Kernel 1: fused QKV projection, tf32, cp.async double-buffered, ldmatrix.
// (unchanged from R11 — validated)
// ---------------------------------------------------------------------------
__global__ void __launch_bounds__(128) proj_tf32_kernel(
    const float* __restrict__ bq, const float* __restrict__ bk,
    const float* __restrict__ bv)
{
    extern __shared__ float sm[];
    float* Xb[2] = { sm,          sm + 8192  };
    float* Wb[2] = { sm + 16384,  sm + 20480 };
    const unsigned smb = (unsigned)__cvta_generic_to_shared(sm);
    const unsigned Xbb[2] = { smb,             smb + 8192u*4  };
    const unsigned Wbb[2] = { smb + 16384u*4,  smb + 20480u*4 };

    const int z  = blockIdx.y;
    const int p  = z / (B*H);
    const int bh = z % (B*H);

    const float* x    = (p == 0 ? g_xq : p == 1 ? g_xk : g_xv) + (size_t)(bh / H) * S * D;
    const float* W    = (p == 0 ? g_wq : p == 1 ? g_wk : g_wv) + (size_t)(bh % H) * A * D;
    const float* bias = (p == 0 ? bq   : p == 1 ? bk   : bv)   + (bh % H) * A;

    const int s0   = blockIdx.x * 128;
    const int tid  = threadIdx.x;
    const int warp = tid >> 5;
    const int lane = tid & 31;
    const int grp  = lane >> 2;
    const int qr   = lane & 3;
    const int laneM = lane >> 3, laneR = lane & 7;
    const unsigned xr   = (unsigned)laneR << 2;
    const unsigned aw0  = (unsigned)(warp*32 + ((laneM&1)<<3) + laneR) * 64;
    const unsigned aw1  = aw0 + 1024;
    const unsigned acol = (unsigned)(laneM >> 1) << 2;
    const unsigned bw   = (unsigned)(((laneM>>1)<<3) + laneR) * 64;
    const unsigned bcol = (unsigned)(laneM & 1) << 2;

    float acc[2][8][4];
    #pragma unroll
    for (int g = 0; g < 2; g++)
        #pragma unroll
        for (int nt = 0; nt < 8; nt++)
            #pragma unroll
            for (int j = 0; j < 4; j++) acc[g][nt][j] = 0.0f;

    {
        #pragma unroll
        for (int u = 0; u < 16; u++) {
            int idx = (u * 128 + tid) * 4;
            int r = idx >> 6, c = idx & 63;
            cpa16(&Xb[0][SWL(r, c)], &x[(size_t)(s0 + r) * D + c]);
        }
        #pragma unroll
        for (int u = 0; u < 8; u++) {
            int idx = (u * 128 + tid) * 4;
            int r = idx >> 6, c = idx & 63;
            cpa16(&Wb[0][SWL(r, c)], &W[(size_t)r * D + c]);
        }
        CPA_COMMIT();
    }

    for (int ci = 0; ci < 8; ci++) {
        if (ci < 7) {
            int k0 = (ci + 1) * 64;
            float* Xd = Xb[(ci + 1) & 1];
            float* Wd = Wb[(ci + 1) & 1];
            #pragma unroll
            for (int u = 0; u < 16; u++) {
                int idx = (u * 128 + tid) * 4;
                int r = idx >> 6, c = idx & 63;
                cpa16(&Xd[SWL(r, c)], &x[(size_t)(s0 + r) * D + k0 + c]);
            }
            #pragma unroll
            for (int u = 0; u < 8; u++) {
                int idx = (u * 128 + tid) * 4;
                int r = idx >> 6, c = idx & 63;
                cpa16(&Wd[SWL(r, c)], &W[(size_t)r * D + k0 + c]);
            }
            CPA_COMMIT();
            CPA_WAIT(1);
        } else {
            CPA_WAIT(0);
        }
        __syncthreads();

        const unsigned Xs = Xbb[ci & 1];
        const unsigned Ws = Wbb[ci & 1];
        #pragma unroll
        for (int ks = 0; ks < 8; ks++) {
            unsigned af0[4], af1[4];
            ldsm4(af0, Xs + ((aw0 + ((ks*8 + acol) ^ xr)) << 2));
            ldsm4(af1, Xs + ((aw1 + ((ks*8 + acol) ^ xr)) << 2));
            #pragma unroll
            for (int np = 0; np < 4; np++) {
                unsigned bf[4];
                ldsm4(bf, Ws + ((bw + np*1024u + ((ks*8 + bcol) ^ xr)) << 2));
                mma_tf32(acc[0][2*np],   af0, bf[0], bf[1]);
                mma_tf32(acc[1][2*np],   af1, bf[0], bf[1]);
                mma_tf32(acc[0][2*np+1], af0, bf[2], bf[3]);
                mma_tf32(acc[1][2*np+1], af1, bf[2], bf[3]);
            }
        }
        __syncthreads();
    }

    if (p != 2) {
        float* out = (p == 0 ? g_q : g_k) + (size_t)bh * S * A;
        #pragma unroll
        for (int g = 0; g < 2; g++) {
            int rb = warp * 32 + g * 16 + grp;
            #pragma unroll
            for (int nt = 0; nt < 8; nt++) {
                int c = nt*8 + 2*qr;
                float2 bv2 = make_float2(bias[c], bias[c+1]);
                *(float2*)&out[(size_t)(s0 + rb) * A + c] = make_float2(
                    __uint_as_float(f2tf(acc[g][nt][0] + bv2.x)),
                    __uint_as_float(f2tf(acc[g][nt][1] + bv2.y)));
                *(float2*)&out[(size_t)(s0 + rb + 8) * A + c] = make_float2(
                    __uint_as_float(f2tf(acc[g][nt][2] + bv2.x)),
                    __uint_as_float(f2tf(acc[g][nt][3] + bv2.y)));
            }
        }
    } else {
        // V: transposed store out_t[a][s]
        float* outT = g_v + (size_t)bh * A * S;
        #pragma unroll
        for (int g = 0; g < 2; g++) {
            int rb = warp * 32 + g * 16 + grp;
            #pragma unroll
            for (int nt = 0; nt < 8; nt++) {
                int c = nt*8 + 2*qr;
                float b0v = bias[c], b1v = bias[c+1];
                outT[(size_t)c     * S + s0 + rb]     =
                    __uint_as_float(f2tf(acc[g][nt][0] + b0v));
                outT[(size_t)(c+1) * S + s0 + rb]     =
                    __uint_as_float(f2tf(acc[g][nt][1] + b1v));
                outT[(size_t)c     * S + s0 + rb + 8] =
                    __uint_as_float(f2tf(acc[g][nt][2] + b0v));
                outT[(size_t)(c+1) * S + s0 + rb + 8] =
                    __uint_as_float(f2tf(acc[g][nt][3] + b1v));
            }
        }
    }
}

// ---------------------------------------------------------------------------
// Kernel 2: flash attention, tf32. REWRITE: 8 warps x 16 rows (256 thr),
// Q fragments register-resident (loaded once), K/V double-buffered cp.async.
// Smem 96KB: K[2] 16K | V[2] 16K | Ps 32K (Ps also stages Q in prologue).
// Causal block-skip (j<=i masked); last CTA (row S-1 fully masked -> uniform
// over ALL S keys) keeps the full loop. grid: (S/128, B*H), 256 threads.
// ---------------------------------------------------------------------------
__global__ void __launch_bounds__(256, 2) attn_mma_kernel()
{
    extern __shared__ float sm[];
    float* Kb[2] = { sm,          sm + 4096 };   // 64*64 each
    float* Vb[2] = { sm + 8192,   sm + 12288 };  // 64*64 each [d][key]
    float* Ps    = sm + 16384;                   // 128*64 (stages Q first)
    const unsigned smb = (unsigned)__cvta_generic_to_shared(sm);
    const unsigned Kbb[2] = { smb,            smb + 4096u*4  };
    const unsigned Vbb[2] = { smb + 8192u*4,  smb + 12288u*4 };
    const unsigned Psb = smb + 16384u*4;

    const int bh = blockIdx.y;
    const int b  = bh / H;
    const int h  = bh % H;
    const int qb = blockIdx.x * 128;
    const int tid  = threadIdx.x;
    const int warp = tid >> 5;          // 0..7, owns rows 16*warp..+15
    const int lane = tid & 31;
    const int grp  = lane >> 2;
    const int qr   = lane & 3;
    const int laneM = lane >> 3, laneR = lane & 7;
    const unsigned xr   = (unsigned)laneR << 2;
    const unsigned aw   = (unsigned)(warp*16 + ((laneM&1)<<3) + laneR) * 64;
    const unsigned acol = (unsigned)(laneM >> 1) << 2;
    const unsigned bw   = (unsigned)(((laneM>>1)<<3) + laneR) * 64;
    const unsigned bcol = (unsigned)(laneM & 1) << 2;

    const float* kg  = g_k + (size_t)bh * S * 64;
    const float* vgt = g_v + (size_t)bh * A * S;   // [d][s]
    const int j_start = (qb == S - 128) ? 0 : qb;
    const int nb = (S - j_start) >> 6;

    // ---- issue K/V block 0 loads first (overlap with Q staging) ----
    #pragma unroll
    for (int u = 0; u < 4; u++) {
        int idx = (u * 256 + tid) * 4;
        int r = idx >> 6, c = idx & 63;
        cpa16(&Kb[0][SWL(r, c)], &kg[(size_t)j_start * 64 + idx]);
        cpa16(&Vb[0][SWL(r, c)], &vgt[(size_t)r * S + j_start + c]);
    }
    CPA_COMMIT();

    // ---- stage Q (scaled by 1/sqrt(A); exact for tf32) into Ps region ----
    const float* qg = g_q + ((size_t)bh * S + qb) * 64;
    #pragma unroll
    for (int u = 0; u < 8; u++) {
        int idx = (u * 256 + tid) * 4;
        int r = idx >> 6, c = idx & 63;
        float4 v = *(const float4*)&qg[idx];
        float* p = &Ps[SWL(r, c)];
        p[0] = v.x * 0.125f; p[1] = v.y * 0.125f;
        p[2] = v.z * 0.125f; p[3] = v.w * 0.125f;
    }
    __syncthreads();

    // ---- load Q fragments once (32 regs) ----
    unsigned qa[8][4];
    #pragma unroll
    for (int ks = 0; ks < 8; ks++)
        ldsm4(qa[ks], Psb + ((aw + ((ks*8 + acol) ^ xr)) << 2));
    __syncwarp();   // frag reads complete before Ps rows are overwritten by P

    float oacc[8][4];
    #pragma unroll
    for (int nt = 0; nt < 8; nt++)
        #pragma unroll
        for (int j = 0; j < 4; j++) oacc[nt][j] = 0.0f;

    float m0 = -INFINITY, m1 = -INFINITY, l0 = 0.0f, l1 = 0.0f;
    const int i0 = qb + warp * 16 + grp;
    const int i1 = i0 + 8;
    const int rb = warp * 16 + grp;

    for (int it = 0; it < nb; it++) {
        const int j0 = j_start + (it << 6);
        // ---- prefetch next block (buffer freed by prev iter's end-sync) ----
        if (it + 1 < nb) {
            int jn = j0 + 64;
            float* Kd = Kb[(it + 1) & 1];
            float* Vd = Vb[(it + 1) & 1];
            #pragma unroll
            for (int u = 0; u < 4; u++) {
                int idx = (u * 256 + tid) * 4;
                int r = idx >> 6, c = idx & 63;
                cpa16(&Kd[SWL(r, c)], &kg[(size_t)jn * 64 + idx]);
                cpa16(&Vd[SWL(r, c)], &vgt[(size_t)r * S + jn + c]);
            }
            CPA_COMMIT();
            CPA_WAIT(1);
        } else {
            CPA_WAIT(0);
        }
        __syncthreads();

        const unsigned Ks = Kbb[it & 1];
        const unsigned Vs = Vbb[it & 1];

        // ---- S = Q * K^T (A from regs, B ldsm) ----
        float sacc[8][4];
        #pragma unroll
        for (int nt = 0; nt < 8; nt++)
            #pragma unroll
            for (int j = 0; j < 4; j++) sacc[nt][j] = 0.0f;

        #pragma unroll
        for (int ks = 0; ks < 8; ks++) {
            #pragma unroll
            for (int np = 0; np < 4; np++) {
                unsigned kb[4];
                ldsm4(kb, Ks + ((bw + np*1024u + ((ks*8 + bcol) ^ xr)) << 2));
                mma_tf32(sacc[2*np],   qa[ks], kb[0], kb[1]);
                mma_tf32(sacc[2*np+1], qa[ks], kb[2], kb[3]);
            }
        }

        // ---- mask + online softmax; P -> Ps (tf32) ----
        float tmax0 = -INFINITY, tmax1 = -INFINITY;
        #pragma unroll
        for (int nt = 0; nt < 8; nt++) {
            int j = j0 + nt*8 + 2*qr;
            if (j     <= i0) sacc[nt][0] = -1.0e9f;
            if (j + 1 <= i0) sacc[nt][1] = -1.0e9f;
            if (j     <= i1) sacc[nt][2] = -1.0e9f;
            if (j + 1 <= i1) sacc[nt][3] = -1.0e9f;
            tmax0 = fmaxf(tmax0, fmaxf(sacc[nt][0], sacc[nt][1]));
            tmax1 = fmaxf(tmax1, fmaxf(sacc[nt][2], sacc[nt][3]));
        }
        tmax0 = fmaxf(tmax0, __shfl_xor_sync(0xffffffffu, tmax0, 1));
        tmax0 = fmaxf(tmax0, __shfl_xor_sync(0xffffffffu, tmax0, 2));
        tmax1 = fmaxf(tmax1, __shfl_xor_sync(0xffffffffu, tmax1, 1));
        tmax1 = fmaxf(tmax1, __shfl_xor_sync(0xffffffffu, tmax1, 2));

        float mn0 = fmaxf(m0, tmax0);
        float mn1 = fmaxf(m1, tmax1);
        float cr0 = __expf(m0 - mn0);   // first block: exp(-inf) = 0
        float cr1 = __expf(m1 - mn1);
        l0 *= cr0; l1 *= cr1;
        m0 = mn0;  m1 = mn1;
        #pragma unroll
        for (int nt = 0; nt < 8; nt++) {
            oacc[nt][0] *= cr0; oacc[nt][1] *= cr0;
            oacc[nt][2] *= cr1; oacc[nt][3] *= cr1;
        }

        float ls0 = 0.0f, ls1 = 0.0f;
        #pragma unroll
        for (int nt = 0; nt < 8; nt++) {
            float p0 = __expf(sacc[nt][0] - mn0);
            float p1 = __expf(sacc[nt][1] - mn0);
            float p2 = __expf(sacc[nt][2] - mn1);
            float p3 = __expf(sacc[nt][3] - mn1);
            ls0 += p0 + p1; ls1 += p2 + p3;
            int c = nt*8 + 2*qr;
            *(float2*)&Ps[SWL(rb, c)] =
                make_float2(__uint_as_float(f2tf(p0)), __uint_as_float(f2tf(p1)));
            *(float2*)&Ps[SWL(rb + 8, c)] =
                make_float2(__uint_as_float(f2tf(p2)), __uint_as_float(f2tf(p3)));
        }
        l0 += ls0; l1 += ls1;
        __syncwarp();   // P rows are warp-private; order stores before loads

        // ---- O += P * V (A ldsm from Ps, B ldsm from Vs) ----
        #pragma unroll
        for (int ks = 0; ks < 8; ks++) {
            unsigned pa[4];
            ldsm4(pa, Psb + ((aw + ((ks*8 + acol) ^ xr)) << 2));
            #pragma unroll
            for (int np = 0; np < 4; np++) {
                unsigned vb[4];
                ldsm4(vb, Vs + ((bw + np*1024u + ((ks*8 + bcol) ^ xr)) << 2));
                mma_tf32(oacc[2*np],   pa, vb[0], vb[1]);
                mma_tf32(oacc[2*np+1], pa, vb[2], vb[3]);
            }
        }
        __syncthreads();   // all warps done with buf (it&1) before it+1 refills
    }

    // ---- quad-reduce softmax denominators ----
    l0 += __shfl_xor_sync(0xffffffffu, l0, 1);
    l0 += __shfl_xor_sync(0xffffffffu, l0, 2);
    l1 += __shfl_xor_sync(0xffffffffu, l1, 1);
    l1 += __shfl_xor_sync(0xffffffffu, l1, 2);

    // ---- epilogue: normalize, round to tf32, write head-concat layout ----
    const float inv0 = 1.0f / l0;
    const float inv1 = 1.0f / l1;
    float* ob0 = g_attn + ((size_t)b * S + i0) * HA + h * A;
    float* ob1 = g_attn + ((size_t)b * S + i1) * HA + h * A;
    #pragma unroll
    for (int nt = 0; nt < 8; nt++) {
        int c = nt*8 + 2*qr;
        *(float2*)&ob0[c] = make_float2(
            __uint_as_float(f2tf(oacc[nt][0] * inv0)),
            __uint_as_float(f2tf(oacc[nt][1] * inv0)));
        *(float2*)&ob1[c] = make_float2(
            __uint_as_float(f2tf(oacc[nt][2] * inv1)),
            __uint_as_float(f2tf(oacc[nt][3] * inv1)));
    }
}

// ---------------------------------------------------------------------------
// Kernel 3: output projection, tf32, cp.async double-buffered, ldmatrix.
// (unchanged from R11 — validated)
// ---------------------------------------------------------------------------
__global__ void __launch_bounds__(128) out_proj_tf32_kernel(
    const float* __restrict__ bo, float* __restrict__ out)
{
    extern __shared__ float sm[];
    float* Xb[2] = { sm,          sm + 8192  };
    float* Wb[2] = { sm + 16384,  sm + 20480 };
    const unsigned smb = (unsigned)__cvta_generic_to_shared(sm);
    const unsigned Xbb[2] = { smb,             smb + 8192u*4  };
    const unsigned Wbb[2] = { smb + 16384u*4,  smb + 20480u*4 };

    const int n0 = blockIdx.x * 64;
    const int s0 = blockIdx.y * 128;
    const int tid  = threadIdx.x;
    const int warp = tid >> 5;
    const int lane = tid & 31;
    const int grp  = lane >> 2;
    const int qr   = lane & 3;
    const int laneM = lane >> 3, laneR = lane & 7;
    const unsigned xr   = (unsigned)laneR << 2;
    const unsigned aw0  = (unsigned)(warp*32 + ((laneM&1)<<3) + laneR) * 64;
    const unsigned aw1  = aw0 + 1024;
    const unsigned acol = (unsigned)(laneM >> 1) << 2;
    const unsigned bw   = (unsigned)(((laneM>>1)<<3) + laneR) * 64;
    const unsigned bcol = (unsigned)(laneM & 1) << 2;

    float acc[2][8][4];
    #pragma unroll
    for (int g = 0; g < 2; g++)
        #pragma unroll
        for (int nt = 0; nt < 8; nt++)
            #pragma unroll
            for (int j = 0; j < 4; j++) acc[g][nt][j] = 0.0f;

    {
        #pragma unroll
        for (int u = 0; u < 16; u++) {
            int idx = (u * 128 + tid) * 4;
            int r = idx >> 6, c = idx & 63;
            cpa16(&Xb[0][SWL(r, c)], &g_attn[(size_t)(s0 + r) * HA + c]);
        }
        #pragma unroll
        for (int u = 0; u < 8; u++) {
            int idx = (u * 128 + tid) * 4;
            int r = idx >> 6, c = idx & 63;
            cpa16(&Wb[0][SWL(r, c)], &g_wo[(size_t)(n0 + r) * HA + c]);
        }
        CPA_COMMIT();
    }

    for (int ci = 0; ci < 8; ci++) {
        if (ci < 7) {
            int k0 = (ci + 1) * 64;
            float* Xd = Xb[(ci + 1) & 1];
            float* Wd = Wb[(ci + 1) & 1];
            #pragma unroll
            for (int u = 0; u < 16; u++) {
                int idx = (u * 128 + tid) * 4;
                int r = idx >> 6, c = idx & 63;
                cpa16(&Xd[SWL(r, c)], &g_attn[(size_t)(s0 + r) * HA + k0 + c]);
            }
            #pragma unroll
            for (int u = 0; u < 8; u++) {
                int idx = (u * 128 + tid) * 4;
                int r = idx >> 6, c = idx & 63;
                cpa16(&Wd[SWL(r, c)], &g_wo[(size_t)(n0 + r) * HA + k0 + c]);
            }
            CPA_COMMIT();
            CPA_WAIT(1);
        } else {
            CPA_WAIT(0);
        }
        __syncthreads();

        const unsigned Xs = Xbb[ci & 1];
        const unsigned Ws = Wbb[ci & 1];
        #pragma unroll
        for (int ks = 0; ks < 8; ks++) {
            unsigned af0[4], af1[4];
            ldsm4(af0, Xs + ((aw0 + ((ks*8 + acol) ^ xr)) << 2));
            ldsm4(af1, Xs + ((aw1 + ((ks*8 + acol) ^ xr)) << 2));
            #pragma unroll
            for (int np = 0; np < 4; np++) {
                unsigned bf[4];
                ldsm4(bf, Ws + ((bw + np*1024u + ((ks*8 + bcol) ^ xr)) << 2));
                mma_tf32(acc[0][2*np],   af0, bf[0], bf[1]);
                mma_tf32(acc[1][2*np],   af1, bf[0], bf[1]);
                mma_tf32(acc[0][2*np+1], af0, bf[2], bf[3]);
                mma_tf32(acc[1][2*np+1], af1, bf[2], bf[3]);
            }
        }
        __syncthreads();
    }

    #pragma unroll
    for (int g = 0; g < 2; g++) {
        int rb = warp * 32 + g * 16 + grp;
        #pragma unroll
        for (int nt = 0; nt < 8; nt++) {
            int c = nt*8 + 2*qr;
            float2 bv2 = make_float2(bo[n0 + c], bo[n0 + c + 1]);
            *(float2*)&out[(size_t)(s0 + rb) * D + n0 + c] =
                make_float2(acc[g][nt][0] + bv2.x, acc[g][nt][1] + bv2.y);
            *(float2*)&out[(size_t)(s0 + rb + 8) * D + n0 + c] =
                make_float2(acc[g][nt][2] + bv2.x, acc[g][nt][3] + bv2.y);
        }
    }
}

// ---------------------------------------------------------------------------
extern "C" void kernel_launch(void* const* d_in, const int* in_sizes, int n_in,
                              void* d_out, int out_size)
{
    const float* query = (const float*)d_in[0];
    const float* key   = (const float*)d_in[1];
    const float* value = (const float*)d_in[2];
    const float* Wq    = (const float*)d_in[3];
    const float* bq    = (const float*)d_in[4];
    const float* Wk    = (const float*)d_in[5];
    const float* bk    = (const float*)d_in[6];
    const float* Wv    = (const float*)d_in[7];
    const float* bv    = (const float*)d_in[8];
    const float* Wo    = (const float*)d_in[9];
    const float* bo    = (const float*)d_in[10];
    float* out = (float*)d_out;

    (void)in_sizes; (void)n_in; (void)out_size;

    // ---- one prep launch: round inputs + transpose-round weights ----
    prep_kernel<<<NXB + 1024, 256>>>(query, key, value, Wq, Wk, Wv, Wo);

    // dynamic smem attribute sets: idempotent, capture-safe, no allocation
    static const int SMEM96 = 24576 * (int)sizeof(float);   // 98304 B
    cudaFuncSetAttribute(proj_tf32_kernel,
                         cudaFuncAttributeMaxDynamicSharedMemorySize, SMEM96);
    cudaFuncSetAttribute(attn_mma_kernel,
                         cudaFuncAttributeMaxDynamicSharedMemorySize, SMEM96);
    cudaFuncSetAttribute(out_proj_tf32_kernel,
                         cudaFuncAttributeMaxDynamicSharedMemorySize, SMEM96);

    proj_tf32_kernel<<<dim3(S / 128, 3 * B * H), 128, SMEM96>>>(bq, bk, bv);

    attn_mma_kernel<<<dim3(S / 128, B * H), 256, SMEM96>>>();

    out_proj_tf32_kernel<<<dim3(D / 64, (B * S) / 128), 128, SMEM96>>>(bo, out);
}

// round 13
// speedup vs baseline: 1.0787x; 1.0787x over previous
#include <cuda_runtime.h>
#include <math.h>

#define B 4
#define S 2048
#define D 512
#define H 8
#define A 64
#define HA (H*A)

// Scratch (allocation-free rule: __device__ globals)
__device__ float g_q[(size_t)B*H*S*A];     // proj outputs, tf32-rounded
__device__ float g_k[(size_t)B*H*S*A];
__device__ float g_v[(size_t)B*H*A*S];     // V TRANSPOSED: [bh][d][s]
__device__ float g_attn[(size_t)B*S*HA];   // attention out, tf32-rounded
// tf32-rounded inputs
__device__ float g_xq[(size_t)B*S*D];
__device__ float g_xk[(size_t)B*S*D];
__device__ float g_xv[(size_t)B*S*D];
// tf32-rounded TRANSPOSED weights (n-major for ldmatrix B-operands)
__device__ float g_wq[(size_t)H*A*D];      // [h][a][d]
__device__ float g_wk[(size_t)H*A*D];
__device__ float g_wv[(size_t)H*A*D];
__device__ float g_wo[(size_t)D*HA];       // [d_out][ha]

// ---------------------------------------------------------------------------
// helpers
// ---------------------------------------------------------------------------
__device__ __forceinline__ unsigned f2tf(float x) {
    unsigned u;
    asm("cvt.rna.tf32.f32 %0, %1;" : "=r"(u) : "f"(x));
    return u;
}

__device__ __forceinline__ void mma_tf32(float c[4], const unsigned a[4],
                                         unsigned b0, unsigned b1) {
    asm volatile("mma.sync.aligned.m16n8k8.row.col.f32.tf32.tf32.f32 "
                 "{%0,%1,%2,%3}, {%4,%5,%6,%7}, {%8,%9}, {%0,%1,%2,%3};"
                 : "+f"(c[0]), "+f"(c[1]), "+f"(c[2]), "+f"(c[3])
                 : "r"(a[0]), "r"(a[1]), "r"(a[2]), "r"(a[3]),
                   "r"(b0), "r"(b1));
}

// ldmatrix x4 on fp32 data viewed as b16.
__device__ __forceinline__ void ldsm4(unsigned r[4], unsigned saddr) {
    asm volatile("ldmatrix.sync.aligned.m8n8.x4.shared.b16 {%0,%1,%2,%3}, [%4];"
                 : "=r"(r[0]), "=r"(r[1]), "=r"(r[2]), "=r"(r[3])
                 : "r"(saddr));
}

__device__ __forceinline__ void cpa16(float* dst_smem, const float* src) {
    unsigned d = (unsigned)__cvta_generic_to_shared(dst_smem);
    asm volatile("cp.async.cg.shared.global [%0], [%1], 16;" :: "r"(d), "l"(src));
}
#define CPA_COMMIT() asm volatile("cp.async.commit_group;")
#define CPA_WAIT(n)  asm volatile("cp.async.wait_group %0;" :: "n"(n))

// SWL: XOR bits [2:4] of word-col by row&7 -> ldmatrix tiles conflict-free.
#define SWL(r, c) ((r)*64 + ((c) ^ (((r)&7) << 2)))
#define FU(x) __float_as_uint(x)

// ---------------------------------------------------------------------------
// Kernel 0: fused prep — round x tensors + transpose-round all weights.
// ---------------------------------------------------------------------------
#define NX4 ((B*S*D)/4)
#define NXB (3*NX4/256)          // 12288 rounding blocks
__global__ void __launch_bounds__(256) prep_kernel(
    const float* __restrict__ q, const float* __restrict__ k,
    const float* __restrict__ v,
    const float* __restrict__ wq, const float* __restrict__ wk,
    const float* __restrict__ wv, const float* __restrict__ wo)
{
    const int bid = blockIdx.x;
    const int tid = threadIdx.x;
    if (bid < NXB) {
        int i = bid * 256 + tid;
        const float* src; float* dst; int off;
        if      (i < 1*NX4) { src = q; dst = g_xq; off = i;         }
        else if (i < 2*NX4) { src = k; dst = g_xk; off = i - NX4;   }
        else                { src = v; dst = g_xv; off = i - 2*NX4; }
        float4 val = ((const float4*)src)[off];
        val.x = __uint_as_float(f2tf(val.x));
        val.y = __uint_as_float(f2tf(val.y));
        val.z = __uint_as_float(f2tf(val.z));
        val.w = __uint_as_float(f2tf(val.w));
        ((float4*)dst)[off] = val;
        return;
    }
    // weight transpose: src MxN (k-major) -> dst NxM (n-major), rounded
    __shared__ float ts[32][33];
    const int t = bid - NXB;
    const float* src; float* dst; int M, N, tr, tc;
    if (t < 768) {
        int p = t / 256, rem = t % 256;
        int h = rem / 32, tile = rem % 32;
        tr = tile % 16; tc = tile / 16;          // 16 x 2 tiles (512x64)
        M = D; N = A;
        src = (p == 0 ? wq : p == 1 ? wk : wv) + (size_t)h * D * A;
        dst = (p == 0 ? g_wq : p == 1 ? g_wk : g_wv) + (size_t)h * A * D;
    } else {
        int u = t - 768;
        tr = u % 16; tc = u / 16;                // 16 x 16 tiles (512x512)
        M = HA; N = D;
        src = wo; dst = g_wo;
    }
    const int tx = tid & 31, ty = tid >> 5;
    #pragma unroll
    for (int i = ty; i < 32; i += 8)
        ts[i][tx] = src[(size_t)(tr*32 + i) * N + tc*32 + tx];
    __syncthreads();
    #pragma unroll
    for (int i = ty; i < 32; i += 8)
        dst[(size_t)(tc*32 + i) * M + tr*32 + tx] =
            __uint_as_float(f2tf(ts[tx][i]));
}

// ---------------------------------------------------------------------------
// Kernel 1: fused QKV projection, tf32, cp.async double-buffered, ldmatrix.
// (unchanged from R11 — validated at 295.7)
// ---------------------------------------------------------------------------
__global__ void __launch_bounds__(128) proj_tf32_kernel(
    const float* __restrict__ bq, const float* __restrict__ bk,
    const float* __restrict__ bv)
{
    extern __shared__ float sm[];
    float* Xb[2] = { sm,          sm + 8192  };
    float* Wb[2] = { sm + 16384,  sm + 20480 };
    const unsigned smb = (unsigned)__cvta_generic_to_shared(sm);
    const unsigned Xbb[2] = { smb,             smb + 8192u*4  };
    const unsigned Wbb[2] = { smb + 16384u*4,  smb + 20480u*4 };

    const int z  = blockIdx.y;
    const int p  = z / (B*H);
    const int bh = z % (B*H);

    const float* x    = (p == 0 ? g_xq : p == 1 ? g_xk : g_xv) + (size_t)(bh / H) * S * D;
    const float* W    = (p == 0 ? g_wq : p == 1 ? g_wk : g_wv) + (size_t)(bh % H) * A * D;
    const float* bias = (p == 0 ? bq   : p == 1 ? bk   : bv)   + (bh % H) * A;

    const int s0   = blockIdx.x * 128;
    const int tid  = threadIdx.x;
    const int warp = tid >> 5;
    const int lane = tid & 31;
    const int grp  = lane >> 2;
    const int qr   = lane & 3;
    const int laneM = lane >> 3, laneR = lane & 7;
    const unsigned xr   = (unsigned)laneR << 2;
    const unsigned aw0  = (unsigned)(warp*32 + ((laneM&1)<<3) + laneR) * 64;
    const unsigned aw1  = aw0 + 1024;
    const unsigned acol = (unsigned)(laneM >> 1) << 2;
    const unsigned bw   = (unsigned)(((laneM>>1)<<3) + laneR) * 64;
    const unsigned bcol = (unsigned)(laneM & 1) << 2;

    float acc[2][8][4];
    #pragma unroll
    for (int g = 0; g < 2; g++)
        #pragma unroll
        for (int nt = 0; nt < 8; nt++)
            #pragma unroll
            for (int j = 0; j < 4; j++) acc[g][nt][j] = 0.0f;

    {
        #pragma unroll
        for (int u = 0; u < 16; u++) {
            int idx = (u * 128 + tid) * 4;
            int r = idx >> 6, c = idx & 63;
            cpa16(&Xb[0][SWL(r, c)], &x[(size_t)(s0 + r) * D + c]);
        }
        #pragma unroll
        for (int u = 0; u < 8; u++) {
            int idx = (u * 128 + tid) * 4;
            int r = idx >> 6, c = idx & 63;
            cpa16(&Wb[0][SWL(r, c)], &W[(size_t)r * D + c]);
        }
        CPA_COMMIT();
    }

    for (int ci = 0; ci < 8; ci++) {
        if (ci < 7) {
            int k0 = (ci + 1) * 64;
            float* Xd = Xb[(ci + 1) & 1];
            float* Wd = Wb[(ci + 1) & 1];
            #pragma unroll
            for (int u = 0; u < 16; u++) {
                int idx = (u * 128 + tid) * 4;
                int r = idx >> 6, c = idx & 63;
                cpa16(&Xd[SWL(r, c)], &x[(size_t)(s0 + r) * D + k0 + c]);
            }
            #pragma unroll
            for (int u = 0; u < 8; u++) {
                int idx = (u * 128 + tid) * 4;
                int r = idx >> 6, c = idx & 63;
                cpa16(&Wd[SWL(r, c)], &W[(size_t)r * D + k0 + c]);
            }
            CPA_COMMIT();
            CPA_WAIT(1);
        } else {
            CPA_WAIT(0);
        }
        __syncthreads();

        const unsigned Xs = Xbb[ci & 1];
        const unsigned Ws = Wbb[ci & 1];
        #pragma unroll
        for (int ks = 0; ks < 8; ks++) {
            unsigned af0[4], af1[4];
            ldsm4(af0, Xs + ((aw0 + ((ks*8 + acol) ^ xr)) << 2));
            ldsm4(af1, Xs + ((aw1 + ((ks*8 + acol) ^ xr)) << 2));
            #pragma unroll
            for (int np = 0; np < 4; np++) {
                unsigned bf[4];
                ldsm4(bf, Ws + ((bw + np*1024u + ((ks*8 + bcol) ^ xr)) << 2));
                mma_tf32(acc[0][2*np],   af0, bf[0], bf[1]);
                mma_tf32(acc[1][2*np],   af1, bf[0], bf[1]);
                mma_tf32(acc[0][2*np+1], af0, bf[2], bf[3]);
                mma_tf32(acc[1][2*np+1], af1, bf[2], bf[3]);
            }
        }
        __syncthreads();
    }

    if (p != 2) {
        float* out = (p == 0 ? g_q : g_k) + (size_t)bh * S * A;
        #pragma unroll
        for (int g = 0; g < 2; g++) {
            int rb = warp * 32 + g * 16 + grp;
            #pragma unroll
            for (int nt = 0; nt < 8; nt++) {
                int c = nt*8 + 2*qr;
                float2 bv2 = make_float2(bias[c], bias[c+1]);
                *(float2*)&out[(size_t)(s0 + rb) * A + c] = make_float2(
                    __uint_as_float(f2tf(acc[g][nt][0] + bv2.x)),
                    __uint_as_float(f2tf(acc[g][nt][1] + bv2.y)));
                *(float2*)&out[(size_t)(s0 + rb + 8) * A + c] = make_float2(
                    __uint_as_float(f2tf(acc[g][nt][2] + bv2.x)),
                    __uint_as_float(f2tf(acc[g][nt][3] + bv2.y)));
            }
        }
    } else {
        // V: transposed store out_t[a][s]
        float* outT = g_v + (size_t)bh * A * S;
        #pragma unroll
        for (int g = 0; g < 2; g++) {
            int rb = warp * 32 + g * 16 + grp;
            #pragma unroll
            for (int nt = 0; nt < 8; nt++) {
                int c = nt*8 + 2*qr;
                float b0v = bias[c], b1v = bias[c+1];
                outT[(size_t)c     * S + s0 + rb]     =
                    __uint_as_float(f2tf(acc[g][nt][0] + b0v));
                outT[(size_t)(c+1) * S + s0 + rb]     =
                    __uint_as_float(f2tf(acc[g][nt][1] + b1v));
                outT[(size_t)c     * S + s0 + rb + 8] =
                    __uint_as_float(f2tf(acc[g][nt][2] + b0v));
                outT[(size_t)(c+1) * S + s0 + rb + 8] =
                    __uint_as_float(f2tf(acc[g][nt][3] + b1v));
            }
        }
    }
}

// ---------------------------------------------------------------------------
// Kernel 2: flash attention — R11 config (128 thr, 4 warps x 32 rows, Qs in
// smem, ldmatrix everywhere) + SPLIT-PHASE K/V PIPELINING with single
// buffers: K(it+1) loads during softmax+PV; V(it+1) loads during next QK.
// Commit order K,V,K,V,... makes wait_group counts exact.
// Smem 96KB: Qs 128x64 | Ks 64x64 | Vs 64x64 [d][key] | Ps 128x64.
// Causal block-skip (j<=i masked); last CTA (row S-1 fully masked -> uniform
// over ALL S keys) keeps the full loop. grid: (S/128, B*H), 128 threads.
// ---------------------------------------------------------------------------
__global__ void __launch_bounds__(128) attn_mma_kernel()
{
    extern __shared__ float sm[];
    float* Qs = sm;              // 128*64
    float* Ks = sm + 8192;       // 64*64
    float* Vs = sm + 12288;      // 64*64  [d][key]
    float* Ps = sm + 16384;      // 128*64
    const unsigned smb = (unsigned)__cvta_generic_to_shared(sm);
    const unsigned Qsb = smb;
    const unsigned Ksb = smb + 8192u*4;
    const unsigned Vsb = smb + 12288u*4;
    const unsigned Psb = smb + 16384u*4;

    const int bh = blockIdx.y;
    const int b  = bh / H;
    const int h  = bh % H;
    const int qb = blockIdx.x * 128;
    const int tid  = threadIdx.x;
    const int warp = tid >> 5;
    const int lane = tid & 31;
    const int grp  = lane >> 2;
    const int qr   = lane & 3;
    const int laneM = lane >> 3, laneR = lane & 7;
    const unsigned xr   = (unsigned)laneR << 2;
    const unsigned aw0  = (unsigned)(warp*32 + ((laneM&1)<<3) + laneR) * 64;
    const unsigned aw1  = aw0 + 1024;
    const unsigned acol = (unsigned)(laneM >> 1) << 2;
    const unsigned bw   = (unsigned)(((laneM>>1)<<3) + laneR) * 64;
    const unsigned bcol = (unsigned)(laneM & 1) << 2;

    const float* kg  = g_k + (size_t)bh * S * 64;
    const float* vgt = g_v + (size_t)bh * A * S;   // [d][s]
    const int j_start = (qb == S - 128) ? 0 : qb;
    const int nb = (S - j_start) >> 6;

    // ---- preload K(0) then V(0) as separate commit groups ----
    #pragma unroll
    for (int u = 0; u < 8; u++) {
        int idx = (u * 128 + tid) * 4;
        int r = idx >> 6, c = idx & 63;
        cpa16(&Ks[SWL(r, c)], &kg[(size_t)j_start * 64 + idx]);
    }
    CPA_COMMIT();                      // group: K(0)
    #pragma unroll
    for (int u = 0; u < 8; u++) {
        int idx = (u * 128 + tid) * 4;
        int r = idx >> 6, c = idx & 63;
        cpa16(&Vs[SWL(r, c)], &vgt[(size_t)r * S + j_start + c]);
    }
    CPA_COMMIT();                      // group: V(0)

    // ---- stage Q (scaled by 1/sqrt(A); exact for tf32 values) ----
    const float* qg = g_q + ((size_t)bh * S + qb) * 64;
    #pragma unroll
    for (int u = 0; u < 16; u++) {
        int idx = (u * 128 + tid) * 4;
        int r = idx >> 6, c = idx & 63;
        float4 v = *(const float4*)&qg[idx];
        float* p = &Qs[SWL(r, c)];
        p[0] = v.x * 0.125f; p[1] = v.y * 0.125f;
        p[2] = v.z * 0.125f; p[3] = v.w * 0.125f;
    }

    float oacc[2][8][4];
    #pragma unroll
    for (int g = 0; g < 2; g++)
        #pragma unroll
        for (int nt = 0; nt < 8; nt++)
            #pragma unroll
            for (int j = 0; j < 4; j++) oacc[g][nt][j] = 0.0f;

    float m[4], l[4];
    #pragma unroll
    for (int q = 0; q < 4; q++) { m[q] = -INFINITY; l[q] = 0.0f; }

    for (int it = 0; it < nb; it++) {
        const int j0 = j_start + (it << 6);

        // ---- K(it) arrived (V(it) may still be in flight) ----
        CPA_WAIT(1);
        __syncthreads();   // Ks visible to all warps (covers Qs on it==0)

        // ---- S = Q * K^T (ldmatrix A and B) ----
        float sacc[2][8][4];
        #pragma unroll
        for (int g = 0; g < 2; g++)
            #pragma unroll
            for (int nt = 0; nt < 8; nt++)
                #pragma unroll
                for (int j = 0; j < 4; j++) sacc[g][nt][j] = 0.0f;

        #pragma unroll
        for (int ks = 0; ks < 8; ks++) {
            unsigned qa0[4], qa1[4];
            ldsm4(qa0, Qsb + ((aw0 + ((ks*8 + acol) ^ xr)) << 2));
            ldsm4(qa1, Qsb + ((aw1 + ((ks*8 + acol) ^ xr)) << 2));
            #pragma unroll
            for (int np = 0; np < 4; np++) {
                unsigned kb[4];
                ldsm4(kb, Ksb + ((bw + np*1024u + ((ks*8 + bcol) ^ xr)) << 2));
                mma_tf32(sacc[0][2*np],   qa0, kb[0], kb[1]);
                mma_tf32(sacc[1][2*np],   qa1, kb[0], kb[1]);
                mma_tf32(sacc[0][2*np+1], qa0, kb[2], kb[3]);
                mma_tf32(sacc[1][2*np+1], qa1, kb[2], kb[3]);
            }
        }
        __syncthreads();   // all warps done reading Ks

        // ---- issue K(it+1) into Ks; overlaps softmax + PV ----
        if (it + 1 < nb) {
            int jn = j0 + 64;
            #pragma unroll
            for (int u = 0; u < 8; u++) {
                int idx = (u * 128 + tid) * 4;
                int r = idx >> 6, c = idx & 63;
                cpa16(&Ks[SWL(r, c)], &kg[(size_t)jn * 64 + idx]);
            }
            CPA_COMMIT();              // group: K(it+1)
        }

        // ---- mask + online softmax per row group; P -> Ps (tf32) ----
        #pragma unroll
        for (int g = 0; g < 2; g++) {
            const int iA = qb + warp * 32 + g * 16 + grp;
            const int iB = iA + 8;
            float tmaxA = -INFINITY, tmaxB = -INFINITY;
            #pragma unroll
            for (int nt = 0; nt < 8; nt++) {
                int j = j0 + nt*8 + 2*qr;
                if (j     <= iA) sacc[g][nt][0] = -1.0e9f;
                if (j + 1 <= iA) sacc[g][nt][1] = -1.0e9f;
                if (j     <= iB) sacc[g][nt][2] = -1.0e9f;
                if (j + 1 <= iB) sacc[g][nt][3] = -1.0e9f;
                tmaxA = fmaxf(tmaxA, fmaxf(sacc[g][nt][0], sacc[g][nt][1]));
                tmaxB = fmaxf(tmaxB, fmaxf(sacc[g][nt][2], sacc[g][nt][3]));
            }
            tmaxA = fmaxf(tmaxA, __shfl_xor_sync(0xffffffffu, tmaxA, 1));
            tmaxA = fmaxf(tmaxA, __shfl_xor_sync(0xffffffffu, tmaxA, 2));
            tmaxB = fmaxf(tmaxB, __shfl_xor_sync(0xffffffffu, tmaxB, 1));
            tmaxB = fmaxf(tmaxB, __shfl_xor_sync(0xffffffffu, tmaxB, 2));

            float mnA = fmaxf(m[2*g],   tmaxA);
            float mnB = fmaxf(m[2*g+1], tmaxB);
            float crA = __expf(m[2*g]   - mnA);   // first block: exp(-inf)=0
            float crB = __expf(m[2*g+1] - mnB);
            l[2*g]   *= crA; l[2*g+1] *= crB;
            m[2*g]    = mnA; m[2*g+1]  = mnB;
            #pragma unroll
            for (int nt = 0; nt < 8; nt++) {
                oacc[g][nt][0] *= crA; oacc[g][nt][1] *= crA;
                oacc[g][nt][2] *= crB; oacc[g][nt][3] *= crB;
            }

            float lsA = 0.0f, lsB = 0.0f;
            int rb = warp * 32 + g * 16 + grp;
            #pragma unroll
            for (int nt = 0; nt < 8; nt++) {
                float p0 = __expf(sacc[g][nt][0] - mnA);
                float p1 = __expf(sacc[g][nt][1] - mnA);
                float p2 = __expf(sacc[g][nt][2] - mnB);
                float p3 = __expf(sacc[g][nt][3] - mnB);
                lsA += p0 + p1; lsB += p2 + p3;
                int c = nt*8 + 2*qr;
                *(float2*)&Ps[SWL(rb, c)] =
                    make_float2(__uint_as_float(f2tf(p0)), __uint_as_float(f2tf(p1)));
                *(float2*)&Ps[SWL(rb + 8, c)] =
                    make_float2(__uint_as_float(f2tf(p2)), __uint_as_float(f2tf(p3)));
            }
            l[2*g] += lsA; l[2*g+1] += lsB;
        }
        __syncwarp();   // P rows are warp-private; order stores before loads

        // ---- V(it) arrived (pending: K(it+1) if committed) ----
        if (it + 1 < nb) { CPA_WAIT(1); } else { CPA_WAIT(0); }
        __syncthreads();   // Vs visible to all warps

        // ---- O += P * V (ldmatrix A and B) ----
        #pragma unroll
        for (int ks = 0; ks < 8; ks++) {
            unsigned pa0[4], pa1[4];
            ldsm4(pa0, Psb + ((aw0 + ((ks*8 + acol) ^ xr)) << 2));
            ldsm4(pa1, Psb + ((aw1 + ((ks*8 + acol) ^ xr)) << 2));
            #pragma unroll
            for (int np = 0; np < 4; np++) {
                unsigned vb[4];
                ldsm4(vb, Vsb + ((bw + np*1024u + ((ks*8 + bcol) ^ xr)) << 2));
                mma_tf32(oacc[0][2*np],   pa0, vb[0], vb[1]);
                mma_tf32(oacc[1][2*np],   pa1, vb[0], vb[1]);
                mma_tf32(oacc[0][2*np+1], pa0, vb[2], vb[3]);
                mma_tf32(oacc[1][2*np+1], pa1, vb[2], vb[3]);
            }
        }
        __syncthreads();   // all warps done reading Vs

        // ---- issue V(it+1) into Vs; overlaps next QK ----
        if (it + 1 < nb) {
            int jn = j0 + 64;
            #pragma unroll
            for (int u = 0; u < 8; u++) {
                int idx = (u * 128 + tid) * 4;
                int r = idx >> 6, c = idx & 63;
                cpa16(&Vs[SWL(r, c)], &vgt[(size_t)r * S + jn + c]);
            }
            CPA_COMMIT();              // group: V(it+1)
        }
    }

    // ---- quad-reduce softmax denominators ----
    #pragma unroll
    for (int q = 0; q < 4; q++) {
        l[q] += __shfl_xor_sync(0xffffffffu, l[q], 1);
        l[q] += __shfl_xor_sync(0xffffffffu, l[q], 2);
    }

    // ---- epilogue: normalize, round to tf32, write head-concat layout ----
    #pragma unroll
    for (int g = 0; g < 2; g++) {
        const int iA = qb + warp * 32 + g * 16 + grp;
        const float invA = 1.0f / l[2*g];
        const float invB = 1.0f / l[2*g+1];
        float* obA = g_attn + ((size_t)b * S + iA) * HA + h * A;
        float* obB = g_attn + ((size_t)b * S + iA + 8) * HA + h * A;
        #pragma unroll
        for (int nt = 0; nt < 8; nt++) {
            int c = nt*8 + 2*qr;
            *(float2*)&obA[c] = make_float2(
                __uint_as_float(f2tf(oacc[g][nt][0] * invA)),
                __uint_as_float(f2tf(oacc[g][nt][1] * invA)));
            *(float2*)&obB[c] = make_float2(
                __uint_as_float(f2tf(oacc[g][nt][2] * invB)),
                __uint_as_float(f2tf(oacc[g][nt][3] * invB)));
        }
    }
}

// ---------------------------------------------------------------------------
// Kernel 3: output projection, tf32, cp.async double-buffered, ldmatrix.
// (unchanged from R11 — validated)
// ---------------------------------------------------------------------------
__global__ void __launch_bounds__(128) out_proj_tf32_kernel(
    const float* __restrict__ bo, float* __restrict__ out)
{
    extern __shared__ float sm[];
    float* Xb[2] = { sm,          sm + 8192  };
    float* Wb[2] = { sm + 16384,  sm + 20480 };
    const unsigned smb = (unsigned)__cvta_generic_to_shared(sm);
    const unsigned Xbb[2] = { smb,             smb + 8192u*4  };
    const unsigned Wbb[2] = { smb + 16384u*4,  smb + 20480u*4 };

    const int n0 = blockIdx.x * 64;
    const int s0 = blockIdx.y * 128;
    const int tid  = threadIdx.x;
    const int warp = tid >> 5;
    const int lane = tid & 31;
    const int grp  = lane >> 2;
    const int qr   = lane & 3;
    const int laneM = lane >> 3, laneR = lane & 7;
    const unsigned xr   = (unsigned)laneR << 2;
    const unsigned aw0  = (unsigned)(warp*32 + ((laneM&1)<<3) + laneR) * 64;
    const unsigned aw1  = aw0 + 1024;
    const unsigned acol = (unsigned)(laneM >> 1) << 2;
    const unsigned bw   = (unsigned)(((laneM>>1)<<3) + laneR) * 64;
    const unsigned bcol = (unsigned)(laneM & 1) << 2;

    float acc[2][8][4];
    #pragma unroll
    for (int g = 0; g < 2; g++)
        #pragma unroll
        for (int nt = 0; nt < 8; nt++)
            #pragma unroll
            for (int j = 0; j < 4; j++) acc[g][nt][j] = 0.0f;

    {
        #pragma unroll
        for (int u = 0; u < 16; u++) {
            int idx = (u * 128 + tid) * 4;
            int r = idx >> 6, c = idx & 63;
            cpa16(&Xb[0][SWL(r, c)], &g_attn[(size_t)(s0 + r) * HA + c]);
        }
        #pragma unroll
        for (int u = 0; u < 8; u++) {
            int idx = (u * 128 + tid) * 4;
            int r = idx >> 6, c = idx & 63;
            cpa16(&Wb[0][SWL(r, c)], &g_wo[(size_t)(n0 + r) * HA + c]);
        }
        CPA_COMMIT();
    }

    for (int ci = 0; ci < 8; ci++) {
        if (ci < 7) {
            int k0 = (ci + 1) * 64;
            float* Xd = Xb[(ci + 1) & 1];
            float* Wd = Wb[(ci + 1) & 1];
            #pragma unroll
            for (int u = 0; u < 16; u++) {
                int idx = (u * 128 + tid) * 4;
                int r = idx >> 6, c = idx & 63;
                cpa16(&Xd[SWL(r, c)], &g_attn[(size_t)(s0 + r) * HA + k0 + c]);
            }
            #pragma unroll
            for (int u = 0; u < 8; u++) {
                int idx = (u * 128 + tid) * 4;
                int r = idx >> 6, c = idx & 63;
                cpa16(&Wd[SWL(r, c)], &g_wo[(size_t)(n0 + r) * HA + k0 + c]);
            }
            CPA_COMMIT();
            CPA_WAIT(1);
        } else {
            CPA_WAIT(0);
        }
        __syncthreads();

        const unsigned Xs = Xbb[ci & 1];
        const unsigned Ws = Wbb[ci & 1];
        #pragma unroll
        for (int ks = 0; ks < 8; ks++) {
            unsigned af0[4], af1[4];
            ldsm4(af0, Xs + ((aw0 + ((ks*8 + acol) ^ xr)) << 2));
            ldsm4(af1, Xs + ((aw1 + ((ks*8 + acol) ^ xr)) << 2));
            #pragma unroll
            for (int np = 0; np < 4; np++) {
                unsigned bf[4];
                ldsm4(bf, Ws + ((bw + np*1024u + ((ks*8 + bcol) ^ xr)) << 2));
                mma_tf32(acc[0][2*np],   af0, bf[0], bf[1]);
                mma_tf32(acc[1][2*np],   af1, bf[0], bf[1]);
                mma_tf32(acc[0][2*np+1], af0, bf[2], bf[3]);
                mma_tf32(acc[1][2*np+1], af1, bf[2], bf[3]);
            }
        }
        __syncthreads();
    }

    #pragma unroll
    for (int g = 0; g < 2; g++) {
        int rb = warp * 32 + g * 16 + grp;
        #pragma unroll
        for (int nt = 0; nt < 8; nt++) {
            int c = nt*8 + 2*qr;
            float2 bv2 = make_float2(bo[n0 + c], bo[n0 + c + 1]);
            *(float2*)&out[(size_t)(s0 + rb) * D + n0 + c] =
                make_float2(acc[g][nt][0] + bv2.x, acc[g][nt][1] + bv2.y);
            *(float2*)&out[(size_t)(s0 + rb + 8) * D + n0 + c] =
                make_float2(acc[g][nt][2] + bv2.x, acc[g][nt][3] + bv2.y);
        }
    }
}

// ---------------------------------------------------------------------------
extern "C" void kernel_launch(void* const* d_in, const int* in_sizes, int n_in,
                              void* d_out, int out_size)
{
    const float* query = (const float*)d_in[0];
    const float* key   = (const float*)d_in[1];
    const float* value = (const float*)d_in[2];
    const float* Wq    = (const float*)d_in[3];
    const float* bq    = (const float*)d_in[4];
    const float* Wk    = (const float*)d_in[5];
    const float* bk    = (const float*)d_in[6];
    const float* Wv    = (const float*)d_in[7];
    const float* bv    = (const float*)d_in[8];
    const float* Wo    = (const float*)d_in[9];
    const float* bo    = (const float*)d_in[10];
    float* out = (float*)d_out;

    (void)in_sizes; (void)n_in; (void)out_size;

    // ---- one prep launch: round inputs + transpose-round weights ----
    prep_kernel<<<NXB + 1024, 256>>>(query, key, value, Wq, Wk, Wv, Wo);

    // dynamic smem attribute sets: idempotent, capture-safe, no allocation
    static const int SMEM96 = 24576 * (int)sizeof(float);   // 98304 B
    cudaFuncSetAttribute(proj_tf32_kernel,
                         cudaFuncAttributeMaxDynamicSharedMemorySize, SMEM96);
    cudaFuncSetAttribute(attn_mma_kernel,
                         cudaFuncAttributeMaxDynamicSharedMemorySize, SMEM96);
    cudaFuncSetAttribute(out_proj_tf32_kernel,
                         cudaFuncAttributeMaxDynamicSharedMemorySize, SMEM96);

    proj_tf32_kernel<<<dim3(S / 128, 3 * B * H), 128, SMEM96>>>(bq, bk, bv);

    attn_mma_kernel<<<dim3(S / 128, B * H), 128, SMEM96>>>();

    out_proj_tf32_kernel<<<dim3(D / 64, (B * S) / 128), 128, SMEM96>>>(bo, out);
}

// round 14
// speedup vs baseline: 1.7468x; 1.6195x over previous
#include <cuda_runtime.h>
#include <cuda_fp16.h>
#include <math.h>

#define B 4
#define S 2048
#define D 512
#define H 8
#define A 64
#define HA (H*A)

// Scratch (allocation-free rule: __device__ globals) — all fp16 now
__device__ __half g_q[(size_t)B*H*S*A];     // Q pre-scaled by 1/8, fp16
__device__ __half g_k[(size_t)B*H*S*A];
__device__ __half g_v[(size_t)B*H*A*S];     // V TRANSPOSED: [bh][d][s]
__device__ __half g_attn[(size_t)B*S*HA];   // attention out, fp16
__device__ __half g_xq[(size_t)B*S*D];
__device__ __half g_xk[(size_t)B*S*D];
__device__ __half g_xv[(size_t)B*S*D];
__device__ __half g_wq[(size_t)H*A*D];      // [h][a][d] (n-major)
__device__ __half g_wk[(size_t)H*A*D];
__device__ __half g_wv[(size_t)H*A*D];
__device__ __half g_wo[(size_t)D*HA];       // [d_out][ha]

// ---------------------------------------------------------------------------
// helpers
// ---------------------------------------------------------------------------
__device__ __forceinline__ void mma_f16(float c[4], const unsigned a[4],
                                        unsigned b0, unsigned b1) {
    asm volatile("mma.sync.aligned.m16n8k16.row.col.f32.f16.f16.f32 "
                 "{%0,%1,%2,%3}, {%4,%5,%6,%7}, {%8,%9}, {%0,%1,%2,%3};"
                 : "+f"(c[0]), "+f"(c[1]), "+f"(c[2]), "+f"(c[3])
                 : "r"(a[0]), "r"(a[1]), "r"(a[2]), "r"(a[3]),
                   "r"(b0), "r"(b1));
}

__device__ __forceinline__ void ldsm4(unsigned r[4], unsigned saddr) {
    asm volatile("ldmatrix.sync.aligned.m8n8.x4.shared.b16 {%0,%1,%2,%3}, [%4];"
                 : "=r"(r[0]), "=r"(r[1]), "=r"(r[2]), "=r"(r[3])
                 : "r"(saddr));
}

__device__ __forceinline__ void cpa16(__half* dst_smem, const __half* src) {
    unsigned d = (unsigned)__cvta_generic_to_shared(dst_smem);
    asm volatile("cp.async.cg.shared.global [%0], [%1], 16;" :: "r"(d), "l"(src));
}
#define CPA_COMMIT() asm volatile("cp.async.commit_group;")
#define CPA_WAIT(n)  asm volatile("cp.async.wait_group %0;" :: "n"(n))

// SWH: half-unit swizzle. Rows are 64 halves = 128B; 16B granule = 8 halves.
// XOR bits [3:5] of half-col by row&7 -> ldmatrix tiles conflict-free,
// 16B cp.async blocks stay contiguous.
#define SWH(r, c) ((r)*64 + ((c) ^ (((r)&7) << 3)))

// ---------------------------------------------------------------------------
// Kernel 0: fused prep — fp32->fp16 convert x tensors + transpose-convert
// all weights.
// ---------------------------------------------------------------------------
#define NX4 ((B*S*D)/4)
#define NXB (3*NX4/256)          // 12288 conversion blocks
__global__ void __launch_bounds__(256) prep_kernel(
    const float* __restrict__ q, const float* __restrict__ k,
    const float* __restrict__ v,
    const float* __restrict__ wq, const float* __restrict__ wk,
    const float* __restrict__ wv, const float* __restrict__ wo)
{
    const int bid = blockIdx.x;
    const int tid = threadIdx.x;
    if (bid < NXB) {
        int i = bid * 256 + tid;
        const float* src; __half* dst; int off;
        if      (i < 1*NX4) { src = q; dst = g_xq; off = i;         }
        else if (i < 2*NX4) { src = k; dst = g_xk; off = i - NX4;   }
        else                { src = v; dst = g_xv; off = i - 2*NX4; }
        float4 val = ((const float4*)src)[off];
        __half2 h01 = __floats2half2_rn(val.x, val.y);
        __half2 h23 = __floats2half2_rn(val.z, val.w);
        ((__half2*)dst)[2*off]     = h01;
        ((__half2*)dst)[2*off + 1] = h23;
        return;
    }
    // weight transpose: src MxN (k-major) -> dst NxM (n-major), fp16
    __shared__ float ts[32][33];
    const int t = bid - NXB;
    const float* src; __half* dst; int M, N, tr, tc;
    if (t < 768) {
        int p = t / 256, rem = t % 256;
        int h = rem / 32, tile = rem % 32;
        tr = tile % 16; tc = tile / 16;          // 16 x 2 tiles (512x64)
        M = D; N = A;
        src = (p == 0 ? wq : p == 1 ? wk : wv) + (size_t)h * D * A;
        dst = (p == 0 ? g_wq : p == 1 ? g_wk : g_wv) + (size_t)h * A * D;
    } else {
        int u = t - 768;
        tr = u % 16; tc = u / 16;                // 16 x 16 tiles (512x512)
        M = HA; N = D;
        src = wo; dst = g_wo;
    }
    const int tx = tid & 31, ty = tid >> 5;
    #pragma unroll
    for (int i = ty; i < 32; i += 8)
        ts[i][tx] = src[(size_t)(tr*32 + i) * N + tc*32 + tx];
    __syncthreads();
    #pragma unroll
    for (int i = ty; i < 32; i += 8)
        dst[(size_t)(tc*32 + i) * M + tr*32 + tx] = __float2half_rn(ts[tx][i]);
}

// ---------------------------------------------------------------------------
// Kernel 1: fused QKV projection, fp16 mma (m16n8k16), cp.async
// double-buffered, ldmatrix. CTA = 128(M) x 64(N=A), 4 warps x 32 rows.
// Q output pre-scaled by 1/8 (exact). V output transposed [a][s].
// Smem 48KB: X[2] 16K | W[2] 8K. grid: (S/128, 3*B*H), 128 threads.
// ---------------------------------------------------------------------------
__global__ void __launch_bounds__(128) proj_f16_kernel(
    const float* __restrict__ bq, const float* __restrict__ bk,
    const float* __restrict__ bv)
{
    extern __shared__ __half smh[];
    __half* Xb[2] = { smh,          smh + 8192  };
    __half* Wb[2] = { smh + 16384,  smh + 20480 };
    const unsigned smb = (unsigned)__cvta_generic_to_shared(smh);
    const unsigned Xbb[2] = { smb,             smb + 8192u*2  };
    const unsigned Wbb[2] = { smb + 16384u*2,  smb + 20480u*2 };

    const int z  = blockIdx.y;
    const int p  = z / (B*H);
    const int bh = z % (B*H);

    const __half* x = (p == 0 ? g_xq : p == 1 ? g_xk : g_xv) + (size_t)(bh / H) * S * D;
    const __half* W = (p == 0 ? g_wq : p == 1 ? g_wk : g_wv) + (size_t)(bh % H) * A * D;
    const float* bias = (p == 0 ? bq : p == 1 ? bk : bv) + (bh % H) * A;
    const float scale = (p == 0) ? 0.125f : 1.0f;

    const int s0   = blockIdx.x * 128;
    const int tid  = threadIdx.x;
    const int warp = tid >> 5;
    const int lane = tid & 31;
    const int grp  = lane >> 2;
    const int qr   = lane & 3;
    const int laneM = lane >> 3, laneR = lane & 7;
    const unsigned xr   = (unsigned)laneR << 3;                    // half units
    const unsigned aw0  = (unsigned)(warp*32 + ((laneM&1)<<3) + laneR) * 64;
    const unsigned aw1  = aw0 + 1024;                              // +16 rows
    const unsigned acol = (unsigned)(laneM >> 1) << 3;
    const unsigned bw   = (unsigned)(((laneM>>1)<<3) + laneR) * 64;
    const unsigned bcol = (unsigned)(laneM & 1) << 3;

    float acc[2][8][4];
    #pragma unroll
    for (int g = 0; g < 2; g++)
        #pragma unroll
        for (int nt = 0; nt < 8; nt++)
            #pragma unroll
            for (int j = 0; j < 4; j++) acc[g][nt][j] = 0.0f;

    {
        #pragma unroll
        for (int u = 0; u < 8; u++) {
            int idx = (u * 128 + tid) * 8;
            int r = idx >> 6, c = idx & 63;
            cpa16(&Xb[0][SWH(r, c)], &x[(size_t)(s0 + r) * D + c]);
        }
        #pragma unroll
        for (int u = 0; u < 4; u++) {
            int idx = (u * 128 + tid) * 8;
            int r = idx >> 6, c = idx & 63;
            cpa16(&Wb[0][SWH(r, c)], &W[(size_t)r * D + c]);
        }
        CPA_COMMIT();
    }

    for (int ci = 0; ci < 8; ci++) {
        if (ci < 7) {
            int k0 = (ci + 1) * 64;
            __half* Xd = Xb[(ci + 1) & 1];
            __half* Wd = Wb[(ci + 1) & 1];
            #pragma unroll
            for (int u = 0; u < 8; u++) {
                int idx = (u * 128 + tid) * 8;
                int r = idx >> 6, c = idx & 63;
                cpa16(&Xd[SWH(r, c)], &x[(size_t)(s0 + r) * D + k0 + c]);
            }
            #pragma unroll
            for (int u = 0; u < 4; u++) {
                int idx = (u * 128 + tid) * 8;
                int r = idx >> 6, c = idx & 63;
                cpa16(&Wd[SWH(r, c)], &W[(size_t)r * D + k0 + c]);
            }
            CPA_COMMIT();
            CPA_WAIT(1);
        } else {
            CPA_WAIT(0);
        }
        __syncthreads();

        const unsigned Xs = Xbb[ci & 1];
        const unsigned Ws = Wbb[ci & 1];
        #pragma unroll
        for (int ks = 0; ks < 4; ks++) {           // k16 steps over 64
            const unsigned K = ks * 16;
            unsigned af0[4], af1[4];
            ldsm4(af0, Xs + ((aw0 + ((K + acol) ^ xr)) << 1));
            ldsm4(af1, Xs + ((aw1 + ((K + acol) ^ xr)) << 1));
            #pragma unroll
            for (int np = 0; np < 4; np++) {
                unsigned bf[4];
                ldsm4(bf, Ws + ((bw + np*1024u + ((K + bcol) ^ xr)) << 1));
                mma_f16(acc[0][2*np],   af0, bf[0], bf[1]);
                mma_f16(acc[1][2*np],   af1, bf[0], bf[1]);
                mma_f16(acc[0][2*np+1], af0, bf[2], bf[3]);
                mma_f16(acc[1][2*np+1], af1, bf[2], bf[3]);
            }
        }
        __syncthreads();
    }

    if (p != 2) {
        __half* out = (p == 0 ? g_q : g_k) + (size_t)bh * S * A;
        #pragma unroll
        for (int g = 0; g < 2; g++) {
            int rb = warp * 32 + g * 16 + grp;
            #pragma unroll
            for (int nt = 0; nt < 8; nt++) {
                int c = nt*8 + 2*qr;
                float b0v = bias[c], b1v = bias[c+1];
                *(__half2*)&out[(size_t)(s0 + rb) * A + c] =
                    __floats2half2_rn((acc[g][nt][0] + b0v) * scale,
                                      (acc[g][nt][1] + b1v) * scale);
                *(__half2*)&out[(size_t)(s0 + rb + 8) * A + c] =
                    __floats2half2_rn((acc[g][nt][2] + b0v) * scale,
                                      (acc[g][nt][3] + b1v) * scale);
            }
        }
    } else {
        // V: transposed store out_t[a][s]
        __half* outT = g_v + (size_t)bh * A * S;
        #pragma unroll
        for (int g = 0; g < 2; g++) {
            int rb = warp * 32 + g * 16 + grp;
            #pragma unroll
            for (int nt = 0; nt < 8; nt++) {
                int c = nt*8 + 2*qr;
                float b0v = bias[c], b1v = bias[c+1];
                outT[(size_t)c     * S + s0 + rb]     = __float2half_rn(acc[g][nt][0] + b0v);
                outT[(size_t)(c+1) * S + s0 + rb]     = __float2half_rn(acc[g][nt][1] + b1v);
                outT[(size_t)c     * S + s0 + rb + 8] = __float2half_rn(acc[g][nt][2] + b0v);
                outT[(size_t)(c+1) * S + s0 + rb + 8] = __float2half_rn(acc[g][nt][3] + b1v);
            }
        }
    }
}

// ---------------------------------------------------------------------------
// Kernel 2: flash attention, fp16 mma. R13 structure: 128 thr, 4 warps x
// 32 rows, split-phase K/V pipelining (K(it+1) during softmax+PV, V(it+1)
// during next QK). Q pre-scaled -> pure cp.async staging, merged with K(0)
// commit group. Smem 48KB: Qs 16K | Ks 8K | Vs 8K [d][key] | Ps 16K.
// Causal block-skip (j<=i masked); last CTA (row S-1 fully masked -> uniform
// over ALL S keys) keeps the full loop. grid: (S/128, B*H), 128 threads.
// ---------------------------------------------------------------------------
__global__ void __launch_bounds__(128) attn_mma_kernel()
{
    extern __shared__ __half smh[];
    __half* Qs = smh;              // 128*64
    __half* Ks = smh + 8192;       // 64*64
    __half* Vs = smh + 12288;      // 64*64  [d][key]
    __half* Ps = smh + 16384;      // 128*64
    const unsigned smb = (unsigned)__cvta_generic_to_shared(smh);
    const unsigned Qsb = smb;
    const unsigned Ksb = smb + 8192u*2;
    const unsigned Vsb = smb + 12288u*2;
    const unsigned Psb = smb + 16384u*2;

    const int bh = blockIdx.y;
    const int b  = bh / H;
    const int h  = bh % H;
    const int qb = blockIdx.x * 128;
    const int tid  = threadIdx.x;
    const int warp = tid >> 5;
    const int lane = tid & 31;
    const int grp  = lane >> 2;
    const int qr   = lane & 3;
    const int laneM = lane >> 3, laneR = lane & 7;
    const unsigned xr   = (unsigned)laneR << 3;
    const unsigned aw0  = (unsigned)(warp*32 + ((laneM&1)<<3) + laneR) * 64;
    const unsigned aw1  = aw0 + 1024;
    const unsigned acol = (unsigned)(laneM >> 1) << 3;
    const unsigned bw   = (unsigned)(((laneM>>1)<<3) + laneR) * 64;
    const unsigned bcol = (unsigned)(laneM & 1) << 3;

    const __half* kg  = g_k + (size_t)bh * S * 64;
    const __half* vgt = g_v + (size_t)bh * A * S;   // [d][s]
    const int j_start = (qb == S - 128) ? 0 : qb;
    const int nb = (S - j_start) >> 6;

    // ---- preload: {Q, K(0)} as one commit group, V(0) as the next ----
    const __half* qg = g_q + ((size_t)bh * S + qb) * 64;
    #pragma unroll
    for (int u = 0; u < 8; u++) {
        int idx = (u * 128 + tid) * 8;
        int r = idx >> 6, c = idx & 63;
        cpa16(&Qs[SWH(r, c)], &qg[idx]);
    }
    #pragma unroll
    for (int u = 0; u < 4; u++) {
        int idx = (u * 128 + tid) * 8;
        int r = idx >> 6, c = idx & 63;
        cpa16(&Ks[SWH(r, c)], &kg[(size_t)j_start * 64 + idx]);
    }
    CPA_COMMIT();                      // group: Q + K(0)
    #pragma unroll
    for (int u = 0; u < 4; u++) {
        int idx = (u * 128 + tid) * 8;
        int r = idx >> 6, c = idx & 63;
        cpa16(&Vs[SWH(r, c)], &vgt[(size_t)r * S + j_start + c]);
    }
    CPA_COMMIT();                      // group: V(0)

    float oacc[2][8][4];
    #pragma unroll
    for (int g = 0; g < 2; g++)
        #pragma unroll
        for (int nt = 0; nt < 8; nt++)
            #pragma unroll
            for (int j = 0; j < 4; j++) oacc[g][nt][j] = 0.0f;

    float m[4], l[4];
    #pragma unroll
    for (int q = 0; q < 4; q++) { m[q] = -INFINITY; l[q] = 0.0f; }

    for (int it = 0; it < nb; it++) {
        const int j0 = j_start + (it << 6);

        // ---- Q+K(it) arrived (V(it) may still be in flight) ----
        CPA_WAIT(1);
        __syncthreads();

        // ---- S = Q * K^T ----
        float sacc[2][8][4];
        #pragma unroll
        for (int g = 0; g < 2; g++)
            #pragma unroll
            for (int nt = 0; nt < 8; nt++)
                #pragma unroll
                for (int j = 0; j < 4; j++) sacc[g][nt][j] = 0.0f;

        #pragma unroll
        for (int ks = 0; ks < 4; ks++) {
            const unsigned K = ks * 16;
            unsigned qa0[4], qa1[4];
            ldsm4(qa0, Qsb + ((aw0 + ((K + acol) ^ xr)) << 1));
            ldsm4(qa1, Qsb + ((aw1 + ((K + acol) ^ xr)) << 1));
            #pragma unroll
            for (int np = 0; np < 4; np++) {
                unsigned kb[4];
                ldsm4(kb, Ksb + ((bw + np*1024u + ((K + bcol) ^ xr)) << 1));
                mma_f16(sacc[0][2*np],   qa0, kb[0], kb[1]);
                mma_f16(sacc[1][2*np],   qa1, kb[0], kb[1]);
                mma_f16(sacc[0][2*np+1], qa0, kb[2], kb[3]);
                mma_f16(sacc[1][2*np+1], qa1, kb[2], kb[3]);
            }
        }
        __syncthreads();   // all warps done reading Ks

        // ---- issue K(it+1) into Ks; overlaps softmax + PV ----
        if (it + 1 < nb) {
            int jn = j0 + 64;
            #pragma unroll
            for (int u = 0; u < 4; u++) {
                int idx = (u * 128 + tid) * 8;
                int r = idx >> 6, c = idx & 63;
                cpa16(&Ks[SWH(r, c)], &kg[(size_t)jn * 64 + idx]);
            }
            CPA_COMMIT();              // group: K(it+1)
        }

        // ---- mask + online softmax per row group; P -> Ps (fp16) ----
        #pragma unroll
        for (int g = 0; g < 2; g++) {
            const int iA = qb + warp * 32 + g * 16 + grp;
            const int iB = iA + 8;
            float tmaxA = -INFINITY, tmaxB = -INFINITY;
            #pragma unroll
            for (int nt = 0; nt < 8; nt++) {
                int j = j0 + nt*8 + 2*qr;
                if (j     <= iA) sacc[g][nt][0] = -1.0e9f;
                if (j + 1 <= iA) sacc[g][nt][1] = -1.0e9f;
                if (j     <= iB) sacc[g][nt][2] = -1.0e9f;
                if (j + 1 <= iB) sacc[g][nt][3] = -1.0e9f;
                tmaxA = fmaxf(tmaxA, fmaxf(sacc[g][nt][0], sacc[g][nt][1]));
                tmaxB = fmaxf(tmaxB, fmaxf(sacc[g][nt][2], sacc[g][nt][3]));
            }
            tmaxA = fmaxf(tmaxA, __shfl_xor_sync(0xffffffffu, tmaxA, 1));
            tmaxA = fmaxf(tmaxA, __shfl_xor_sync(0xffffffffu, tmaxA, 2));
            tmaxB = fmaxf(tmaxB, __shfl_xor_sync(0xffffffffu, tmaxB, 1));
            tmaxB = fmaxf(tmaxB, __shfl_xor_sync(0xffffffffu, tmaxB, 2));

            float mnA = fmaxf(m[2*g],   tmaxA);
            float mnB = fmaxf(m[2*g+1], tmaxB);
            float crA = __expf(m[2*g]   - mnA);   // first block: exp(-inf)=0
            float crB = __expf(m[2*g+1] - mnB);
            l[2*g]   *= crA; l[2*g+1] *= crB;
            m[2*g]    = mnA; m[2*g+1]  = mnB;
            #pragma unroll
            for (int nt = 0; nt < 8; nt++) {
                oacc[g][nt][0] *= crA; oacc[g][nt][1] *= crA;
                oacc[g][nt][2] *= crB; oacc[g][nt][3] *= crB;
            }

            float lsA = 0.0f, lsB = 0.0f;
            int rb = warp * 32 + g * 16 + grp;
            #pragma unroll
            for (int nt = 0; nt < 8; nt++) {
                float p0 = __expf(sacc[g][nt][0] - mnA);
                float p1 = __expf(sacc[g][nt][1] - mnA);
                float p2 = __expf(sacc[g][nt][2] - mnB);
                float p3 = __expf(sacc[g][nt][3] - mnB);
                lsA += p0 + p1; lsB += p2 + p3;
                int c = nt*8 + 2*qr;
                *(__half2*)&Ps[SWH(rb, c)]     = __floats2half2_rn(p0, p1);
                *(__half2*)&Ps[SWH(rb + 8, c)] = __floats2half2_rn(p2, p3);
            }
            l[2*g] += lsA; l[2*g+1] += lsB;
        }
        __syncwarp();   // P rows are warp-private; order stores before loads

        // ---- V(it) arrived (pending: K(it+1) if committed) ----
        if (it + 1 < nb) { CPA_WAIT(1); } else { CPA_WAIT(0); }
        __syncthreads();

        // ---- O += P * V ----
        #pragma unroll
        for (int ks = 0; ks < 4; ks++) {
            const unsigned K = ks * 16;
            unsigned pa0[4], pa1[4];
            ldsm4(pa0, Psb + ((aw0 + ((K + acol) ^ xr)) << 1));
            ldsm4(pa1, Psb + ((aw1 + ((K + acol) ^ xr)) << 1));
            #pragma unroll
            for (int np = 0; np < 4; np++) {
                unsigned vb[4];
                ldsm4(vb, Vsb + ((bw + np*1024u + ((K + bcol) ^ xr)) << 1));
                mma_f16(oacc[0][2*np],   pa0, vb[0], vb[1]);
                mma_f16(oacc[1][2*np],   pa1, vb[0], vb[1]);
                mma_f16(oacc[0][2*np+1], pa0, vb[2], vb[3]);
                mma_f16(oacc[1][2*np+1], pa1, vb[2], vb[3]);
            }
        }
        __syncthreads();   // all warps done reading Vs

        // ---- issue V(it+1) into Vs; overlaps next QK ----
        if (it + 1 < nb) {
            int jn = j0 + 64;
            #pragma unroll
            for (int u = 0; u < 4; u++) {
                int idx = (u * 128 + tid) * 8;
                int r = idx >> 6, c = idx & 63;
                cpa16(&Vs[SWH(r, c)], &vgt[(size_t)r * S + jn + c]);
            }
            CPA_COMMIT();              // group: V(it+1)
        }
    }

    // ---- quad-reduce softmax denominators ----
    #pragma unroll
    for (int q = 0; q < 4; q++) {
        l[q] += __shfl_xor_sync(0xffffffffu, l[q], 1);
        l[q] += __shfl_xor_sync(0xffffffffu, l[q], 2);
    }

    // ---- epilogue: normalize, fp16, head-concat layout ----
    #pragma unroll
    for (int g = 0; g < 2; g++) {
        const int iA = qb + warp * 32 + g * 16 + grp;
        const float invA = 1.0f / l[2*g];
        const float invB = 1.0f / l[2*g+1];
        __half* obA = g_attn + ((size_t)b * S + iA) * HA + h * A;
        __half* obB = g_attn + ((size_t)b * S + iA + 8) * HA + h * A;
        #pragma unroll
        for (int nt = 0; nt < 8; nt++) {
            int c = nt*8 + 2*qr;
            *(__half2*)&obA[c] = __floats2half2_rn(oacc[g][nt][0] * invA,
                                                   oacc[g][nt][1] * invA);
            *(__half2*)&obB[c] = __floats2half2_rn(oacc[g][nt][2] * invB,
                                                   oacc[g][nt][3] * invB);
        }
    }
}

// ---------------------------------------------------------------------------
// Kernel 3: output projection, fp16 mma, cp.async double-buffered, ldmatrix.
// out[M=B*S, N=D] = g_attn[M, HA] @ Wo + bo ; Wo pre-transposed [d][ha].
// Smem 48KB. grid: (D/64, B*S/128), 128 threads, 32-row warp tiles.
// Output fp32 (bias added in fp32).
// ---------------------------------------------------------------------------
__global__ void __launch_bounds__(128) out_proj_f16_kernel(
    const float* __restrict__ bo, float* __restrict__ out)
{
    extern __shared__ __half smh[];
    __half* Xb[2] = { smh,          smh + 8192  };
    __half* Wb[2] = { smh + 16384,  smh + 20480 };
    const unsigned smb = (unsigned)__cvta_generic_to_shared(smh);
    const unsigned Xbb[2] = { smb,             smb + 8192u*2  };
    const unsigned Wbb[2] = { smb + 16384u*2,  smb + 20480u*2 };

    const int n0 = blockIdx.x * 64;
    const int s0 = blockIdx.y * 128;
    const int tid  = threadIdx.x;
    const int warp = tid >> 5;
    const int lane = tid & 31;
    const int grp  = lane >> 2;
    const int qr   = lane & 3;
    const int laneM = lane >> 3, laneR = lane & 7;
    const unsigned xr   = (unsigned)laneR << 3;
    const unsigned aw0  = (unsigned)(warp*32 + ((laneM&1)<<3) + laneR) * 64;
    const unsigned aw1  = aw0 + 1024;
    const unsigned acol = (unsigned)(laneM >> 1) << 3;
    const unsigned bw   = (unsigned)(((laneM>>1)<<3) + laneR) * 64;
    const unsigned bcol = (unsigned)(laneM & 1) << 3;

    float acc[2][8][4];
    #pragma unroll
    for (int g = 0; g < 2; g++)
        #pragma unroll
        for (int nt = 0; nt < 8; nt++)
            #pragma unroll
            for (int j = 0; j < 4; j++) acc[g][nt][j] = 0.0f;

    {
        #pragma unroll
        for (int u = 0; u < 8; u++) {
            int idx = (u * 128 + tid) * 8;
            int r = idx >> 6, c = idx & 63;
            cpa16(&Xb[0][SWH(r, c)], &g_attn[(size_t)(s0 + r) * HA + c]);
        }
        #pragma unroll
        for (int u = 0; u < 4; u++) {
            int idx = (u * 128 + tid) * 8;
            int r = idx >> 6, c = idx & 63;
            cpa16(&Wb[0][SWH(r, c)], &g_wo[(size_t)(n0 + r) * HA + c]);
        }
        CPA_COMMIT();
    }

    for (int ci = 0; ci < 8; ci++) {
        if (ci < 7) {
            int k0 = (ci + 1) * 64;
            __half* Xd = Xb[(ci + 1) & 1];
            __half* Wd = Wb[(ci + 1) & 1];
            #pragma unroll
            for (int u = 0; u < 8; u++) {
                int idx = (u * 128 + tid) * 8;
                int r = idx >> 6, c = idx & 63;
                cpa16(&Xd[SWH(r, c)], &g_attn[(size_t)(s0 + r) * HA + k0 + c]);
            }
            #pragma unroll
            for (int u = 0; u < 4; u++) {
                int idx = (u * 128 + tid) * 8;
                int r = idx >> 6, c = idx & 63;
                cpa16(&Wd[SWH(r, c)], &g_wo[(size_t)(n0 + r) * HA + k0 + c]);
            }
            CPA_COMMIT();
            CPA_WAIT(1);
        } else {
            CPA_WAIT(0);
        }
        __syncthreads();

        const unsigned Xs = Xbb[ci & 1];
        const unsigned Ws = Wbb[ci & 1];
        #pragma unroll
        for (int ks = 0; ks < 4; ks++) {
            const unsigned K = ks * 16;
            unsigned af0[4], af1[4];
            ldsm4(af0, Xs + ((aw0 + ((K + acol) ^ xr)) << 1));
            ldsm4(af1, Xs + ((aw1 + ((K + acol) ^ xr)) << 1));
            #pragma unroll
            for (int np = 0; np < 4; np++) {
                unsigned bf[4];
                ldsm4(bf, Ws + ((bw + np*1024u + ((K + bcol) ^ xr)) << 1));
                mma_f16(acc[0][2*np],   af0, bf[0], bf[1]);
                mma_f16(acc[1][2*np],   af1, bf[0], bf[1]);
                mma_f16(acc[0][2*np+1], af0, bf[2], bf[3]);
                mma_f16(acc[1][2*np+1], af1, bf[2], bf[3]);
            }
        }
        __syncthreads();
    }

    #pragma unroll
    for (int g = 0; g < 2; g++) {
        int rb = warp * 32 + g * 16 + grp;
        #pragma unroll
        for (int nt = 0; nt < 8; nt++) {
            int c = nt*8 + 2*qr;
            float2 bv2 = make_float2(bo[n0 + c], bo[n0 + c + 1]);
            *(float2*)&out[(size_t)(s0 + rb) * D + n0 + c] =
                make_float2(acc[g][nt][0] + bv2.x, acc[g][nt][1] + bv2.y);
            *(float2*)&out[(size_t)(s0 + rb + 8) * D + n0 + c] =
                make_float2(acc[g][nt][2] + bv2.x, acc[g][nt][3] + bv2.y);
        }
    }
}

// ---------------------------------------------------------------------------
extern "C" void kernel_launch(void* const* d_in, const int* in_sizes, int n_in,
                              void* d_out, int out_size)
{
    const float* query = (const float*)d_in[0];
    const float* key   = (const float*)d_in[1];
    const float* value = (const float*)d_in[2];
    const float* Wq    = (const float*)d_in[3];
    const float* bq    = (const float*)d_in[4];
    const float* Wk    = (const float*)d_in[5];
    const float* bk    = (const float*)d_in[6];
    const float* Wv    = (const float*)d_in[7];
    const float* bv    = (const float*)d_in[8];
    const float* Wo    = (const float*)d_in[9];
    const float* bo    = (const float*)d_in[10];
    float* out = (float*)d_out;

    (void)in_sizes; (void)n_in; (void)out_size;

    // ---- one prep launch: convert inputs + transpose-convert weights ----
    prep_kernel<<<NXB + 1024, 256>>>(query, key, value, Wq, Wk, Wv, Wo);

    // dynamic smem attribute sets: idempotent, capture-safe, no allocation
    static const int SMEM48 = 24576 * (int)sizeof(__half);   // 49152 B
    cudaFuncSetAttribute(proj_f16_kernel,
                         cudaFuncAttributeMaxDynamicSharedMemorySize, SMEM48);
    cudaFuncSetAttribute(attn_mma_kernel,
                         cudaFuncAttributeMaxDynamicSharedMemorySize, SMEM48);
    cudaFuncSetAttribute(out_proj_f16_kernel,
                         cudaFuncAttributeMaxDynamicSharedMemorySize, SMEM48);

    proj_f16_kernel<<<dim3(S / 128, 3 * B * H), 128, SMEM48>>>(bq, bk, bv);

    attn_mma_kernel<<<dim3(S / 128, B * H), 128, SMEM48>>>();

    out_proj_f16_kernel<<<dim3(D / 64, (B * S) / 128), 128, SMEM48>>>(bo, out);
}